// round 14
// baseline (speedup 1.0000x reference)
#include <cuda_runtime.h>
#include <cuda_fp16.h>
#include <math.h>
#include <stdint.h>

#define SEQT 1024
#define NB   256
#define NIN  256
#define NH   512
#define NSW  128
#define NSD  64
#define NG   2048            // 4*NH
#define KZ   768             // NH + NIN
#define NROWS 2240
#define NTOT 2179
#define NBLK 140             // 70 N-tiles x 2 M-halves
#define NKC  48              // 768/16
#define NTHR 512
#define GSTRIDE (NBLK * NTHR)

// phase A W fragment slice per nT (fp16): [kc(48)][nh(2)][lane(32)][8 halfs] = 24576 halfs
#define WSLICE_H 24576
// Z fragment: [kc(48)][mtile(16)][lane(32)][8 halfs]
#define ZTOT_H  196608
// phase B W_s fragment slice per u0: [kc(8)][ntp(4)][lane(32)][8 halfs]
#define WS_H 8192

// dynamic smem layout (bytes)
#define SMW     0                  // 49152: phase A W fragments
#define SMWS    49152              // 16384: phase B W_s fragments
#define SMSF    65536              // 16384: stack_top fp16 A fragments
#define SMGT    81920              // 16384: gates f32 [64][64]
#define SMCF    98304              // 3072:  cf[3][256] current step
#define SMCFO   101376             // 3072:  cf[3][256] previous step (blend)
#define SMTOTAL 104448

// ---- device scratch ----
__device__ __half g_Wfrag[70 * WSLICE_H];
__device__ __half g_WSfrag[32 * WS_H];
__device__ __half g_Zfrag[ZTOT_H];
__device__ float g_bz[NROWS];
__device__ float g_G1[NB * NG];
__device__ float g_dv[2][NB * NSW];   // double-buffered (blend lags one step)
__device__ float g_ctrl[NB * 3];
__device__ float g_cf[2][3 * NB];     // double-buffered softmax coefficients
__device__ float g_c[NB * NH];
__device__ float g_stk[2][NB * NSD * NSW];
__device__ unsigned g_flags[NBLK * 32];

// ---- helpers ----
__device__ __forceinline__ float sigf(float x) { return 1.f / (1.f + expf(-x)); }
__device__ __forceinline__ void store_zfrag(int b, int kk, float v) {
    int kc = kk >> 4, ko = kk & 15;
    int t   = ((b & 7) << 2) | ((ko & 7) >> 1);
    int reg = ((b >> 3) & 1) | (((ko >> 3) & 1) << 1);
    int idx = ((kc * 16 + (b >> 4)) * 32 + t) * 8 + reg * 2 + (ko & 1);
    g_Zfrag[idx] = __float2half(v);
}
__device__ __forceinline__ void store_zfrag2(int b, int kk, float v0, float v1) {
    int kc = kk >> 4, ko = kk & 15;
    int t   = ((b & 7) << 2) | ((ko & 7) >> 1);
    int reg = ((b >> 3) & 1) | (((ko >> 3) & 1) << 1);
    int idx = ((kc * 16 + (b >> 4)) * 32 + t) * 8 + reg * 2;
    *(__half2*)&g_Zfrag[idx] = __floats2half2_rn(v0, v1);
}
__device__ __forceinline__ void store_sfrag2(__half* base, int bl, int k, float v0, float v1) {
    int kc = k >> 4, ko = k & 15;
    int mt = bl >> 4, bm = bl & 15;
    int t   = ((bm & 7) << 2) | ((ko & 7) >> 1);
    int reg = ((bm >> 3) & 1) | (((ko >> 3) & 1) << 1);
    int idx = ((kc * 4 + mt) * 32 + t) * 8 + reg * 2;
    *(__half2*)&base[idx] = __floats2half2_rn(v0, v1);
}

#define MMA_F16(acc, A, b0, b1) asm volatile( \
    "mma.sync.aligned.m16n8k16.row.col.f32.f16.f16.f32 " \
    "{%0,%1,%2,%3},{%4,%5,%6,%7},{%8,%9},{%0,%1,%2,%3};" \
    : "+f"(acc[0]), "+f"(acc[1]), "+f"(acc[2]), "+f"(acc[3]) \
    : "r"(A.x), "r"(A.y), "r"(A.z), "r"(A.w), "r"(b0), "r"(b1))

#define BAR1() asm volatile("bar.sync 1, 256;" ::: "memory")   // lower 256 (gates)
#define BAR2() asm volatile("bar.sync 2, 128;" ::: "memory")   // MMA warps (ctrl)
#define BAR3() asm volatile("bar.sync 3, 384;" ::: "memory")   // blend warps (cf)

// ---- distributed-flag grid barrier ----
__device__ __forceinline__ void grid_bar(int epoch) {
    const unsigned tgt = (unsigned)(epoch + 1);
    __syncthreads();
    if (threadIdx.x == 0) {
        asm volatile("st.release.gpu.u32 [%0], %1;"
                     :: "l"(&g_flags[blockIdx.x * 32]), "r"(tgt) : "memory");
    }
    if (threadIdx.x < NBLK) {
        unsigned v;
        do {
            asm volatile("ld.acquire.gpu.u32 %0, [%1];"
                         : "=r"(v) : "l"(&g_flags[threadIdx.x * 32]) : "memory");
        } while (v < tgt);
    }
    __syncthreads();
}

__device__ __forceinline__ float wval(int n, int k,
        const float* Whh, const float* Wih, const float* Dw, const float* Aw) {
    if (n < NG)        return (k < NH) ? Whh[n*NH + k] : Wih[n*(NIN+NSW) + (k-NH)];
    if (n < NG + NSW)  return (k < NH) ? Dw[(n-NG)*NH + k] : 0.f;
    if (n < NTOT)      return (k < NH) ? Aw[(n-NG-NSW)*NH + k] : 0.f;
    return 0.f;
}

// blend(tb): stk[tb&1] -> stk[(tb+1)&1] using cf(tb), dv(tb). 384 threads (ut 0..383).
__device__ __forceinline__ void run_blend(int tb, int bx, int ut, const float* cfo) {
    const float* __restrict__ sold = g_stk[tb & 1];
    float* __restrict__ snew = g_stk[(tb + 1) & 1];
    const float* __restrict__ dvO = g_dv[tb & 1];
    const int TOTR = NB * 8 * 32;
    int lo_ = (int)((long long)bx * TOTR / NBLK);
    int hi_ = (int)((long long)(bx + 1) * TOTR / NBLK);
    const float4 z4 = make_float4(0.f, 0.f, 0.f, 0.f);
    for (int run = lo_ + ut; run < hi_; run += 384) {
        int ww = run & 31;
        int q = run >> 5;
        int b = q >> 3, dr = q & 7;
        int d0 = dr << 3;
        float pu = cfo[b], po = cfo[256 + b], no = cfo[512 + b];
        const float* cb = &sold[b * NSD * NSW + ww * 4];
        float* ob = &snew[(b * NSD + d0) * NSW + ww * 4];
        float4 v[6];
        v[0] = d0 ? __ldcg((const float4*)(cb + (d0 - 1) * NSW))
                  : __ldcg((const float4*)&dvO[b * NSW + ww * 4]);
#pragma unroll
        for (int i = 0; i < 5; i++)
            v[i + 1] = __ldcg((const float4*)(cb + (d0 + i) * NSW));
#pragma unroll
        for (int i = 0; i < 4; i++) {
            float4 o;
            o.x = no * v[i+1].x + pu * v[i].x + po * v[i+2].x;
            o.y = no * v[i+1].y + pu * v[i].y + po * v[i+2].y;
            o.z = no * v[i+1].z + pu * v[i].z + po * v[i+2].z;
            o.w = no * v[i+1].w + pu * v[i].w + po * v[i+2].w;
            *(float4*)(ob + i * NSW) = o;
        }
        v[0] = v[4]; v[1] = v[5];
#pragma unroll
        for (int i = 0; i < 3; i++)
            v[i + 2] = __ldcg((const float4*)(cb + (d0 + 5 + i) * NSW));
        v[5] = (d0 + 8 < NSD) ? __ldcg((const float4*)(cb + (d0 + 8) * NSW)) : z4;
#pragma unroll
        for (int i = 0; i < 4; i++) {
            float4 o;
            o.x = no * v[i+1].x + pu * v[i].x + po * v[i+2].x;
            o.y = no * v[i+1].y + pu * v[i].y + po * v[i+2].y;
            o.z = no * v[i+1].z + pu * v[i].z + po * v[i+2].z;
            o.w = no * v[i+1].w + pu * v[i].w + po * v[i+2].w;
            *(float4*)(ob + (4 + i) * NSW) = o;
        }
    }
}

// ================= persistent kernel =================
__global__ void __launch_bounds__(NTHR, 1) rnn_persist(
    const float* __restrict__ x, const float* __restrict__ h0,
    float* __restrict__ outs, const float* __restrict__ Wih,
    const float* __restrict__ Whh, const float* __restrict__ Dw,
    const float* __restrict__ Aw,  const float* __restrict__ bih,
    const float* __restrict__ bhh, const float* __restrict__ Db,
    const float* __restrict__ Ab) {
    extern __shared__ char smem[];
    const int tid = threadIdx.x, bx = blockIdx.x;
    const int lane = tid & 31, w = tid >> 5;
    const int gtid = bx * NTHR + tid;

    // ---------- setup ----------
    {
        const long long WTOT = 70LL * WSLICE_H;
        for (long long i = gtid; i < WTOT; i += GSTRIDE) {
            int s = (int)(i / WSLICE_H);
            int j = (int)(i - (long long)s * WSLICE_H);
            int sub = j & 7, lane2 = (j >> 3) & 31, nh2 = (j >> 8) & 1, kc = j >> 9;
            int nt = nh2 * 2 + (sub >> 2);
            int jj = sub & 3;
            int nrow = s * 32 + nt * 8 + (lane2 >> 2);
            int kk = kc * 16 + (lane2 & 3) * 2 + ((jj >> 1) << 3) + (jj & 1);
            g_Wfrag[i] = __float2half(wval(nrow, kk, Whh, Wih, Dw, Aw));
        }
        for (int i = gtid; i < 32 * WS_H; i += GSTRIDE) {
            int s = i >> 13, j = i & (WS_H - 1);
            int sub = j & 7, lane2 = (j >> 3) & 31, ntp = (j >> 8) & 3, kc = j >> 10;
            int nt = ntp * 2 + (sub >> 2);
            int jj = sub & 3;
            int col = nt * 8 + (lane2 >> 2);
            int g = col >> 4, uu = col & 15;
            int jrow = g * NH + s * 16 + uu;
            int kk = kc * 16 + (lane2 & 3) * 2 + ((jj >> 1) << 3) + (jj & 1);
            g_WSfrag[i] = __float2half(Wih[jrow * (NIN + NSW) + NIN + kk]);
        }
        if (gtid < NROWS) {
            float b = 0.f;
            if (gtid < NG)          b = bih[gtid] + bhh[gtid];
            else if (gtid < NG+NSW) b = Db[gtid-NG];
            else if (gtid < NTOT)   b = Ab[gtid-NG-NSW];
            g_bz[gtid] = b;
        }
        for (int i = gtid; i < NB * NH; i += GSTRIDE)
            store_zfrag(i >> 9, i & 511, h0[i]);
        for (int i = gtid; i < NB * NIN; i += GSTRIDE)
            store_zfrag(i >> 8, 512 + (i & 255), x[i]);
    }
    grid_bar(0);

    const int nT = bx % 70, mT = bx / 70;
    const int n0 = nT * 32;
    const int wl = w & 3;                  // MMA warp id 0..3

    // load resident phase-A W slice (48 KB)
    {
        const uint4* src = (const uint4*)(g_Wfrag + (size_t)nT * WSLICE_H);
        uint4* dst = (uint4*)(smem + SMW);
#pragma unroll
        for (int i = 0; i < 6; i++) {
            uint4 v; const uint4* p = src + tid + i * NTHR;
            asm volatile("ld.global.cg.v4.u32 {%0,%1,%2,%3}, [%4];"
                         : "=r"(v.x), "=r"(v.y), "=r"(v.z), "=r"(v.w) : "l"(p));
            dst[tid + i * NTHR] = v;
        }
    }
    if (bx < 128) {
        const uint4* src = (const uint4*)(g_WSfrag + (size_t)(bx & 31) * WS_H);
        uint4* dst = (uint4*)(smem + SMWS);
#pragma unroll
        for (int i = 0; i < 2; i++) {
            uint4 v; const uint4* p = src + tid + i * NTHR;
            asm volatile("ld.global.cg.v4.u32 {%0,%1,%2,%3}, [%4];"
                         : "=r"(v.x), "=r"(v.y), "=r"(v.z), "=r"(v.w) : "l"(p));
            dst[tid + i * NTHR] = v;
        }
    }
    __syncthreads();

    const char* pB = smem + SMW + lane * 16;
    const char* pA0 = (const char*)g_Zfrag + (size_t)(mT * 8 + wl * 2) * 512 + lane * 16;
    const char* pA1 = pA0 + 512;
    __half* Sfrag  = (__half*)(smem + SMSF);
    float*  gates_s = (float*)(smem + SMGT);
    float*  cfs    = (float*)(smem + SMCF);    // current step (gates path)
    float*  cfo    = (float*)(smem + SMCFO);   // previous step (blend path)

    // phase A epilogue constants
    const int er = lane >> 2, ec2 = (lane & 3) << 1;
    const int ebase = mT * 128 + wl * 32 + er;   // mtile0 rows: ebase, ebase+8; mtile1: +16, +24
    float bzv[4][2];
#pragma unroll
    for (int q = 0; q < 4; q++) {
        int col = n0 + q * 8 + ec2;
        bzv[q][0] = g_bz[col]; bzv[q][1] = g_bz[col + 1];
    }

    int ep = 1;
    for (int t = 0; t < SEQT; t++) {
        // ======== phase A window: warps 0-3 MMA(t) (2 mtiles each) || warps 4-15 blend(t-1) ========
        if (w < 4) {
            float acc[2][4][4];
#pragma unroll
            for (int m = 0; m < 2; m++)
#pragma unroll
                for (int q = 0; q < 4; q++)
#pragma unroll
                    for (int r = 0; r < 4; r++) acc[m][q][r] = 0.f;

            uint4 a0[4], a1[4];
#pragma unroll
            for (int p = 0; p < 4; p++) {
                a0[p] = __ldcg((const uint4*)(pA0 + p * 8192));
                a1[p] = __ldcg((const uint4*)(pA1 + p * 8192));
            }
            uint4 bw0 = *(const uint4*)(pB);
            uint4 bw1 = *(const uint4*)(pB + 512);

            for (int kc = 0; kc < NKC; kc++) {
                uint4 A0 = a0[kc & 3], A1 = a1[kc & 3];
                if (kc < NKC - 4) {
                    a0[kc & 3] = __ldcg((const uint4*)(pA0 + (kc + 4) * 8192));
                    a1[kc & 3] = __ldcg((const uint4*)(pA1 + (kc + 4) * 8192));
                }
                uint4 c0 = bw0, c1 = bw1;
                if (kc < NKC - 1) {
                    bw0 = *(const uint4*)(pB + (((kc + 1) * 2) << 9));
                    bw1 = *(const uint4*)(pB + (((kc + 1) * 2 + 1) << 9));
                }
                MMA_F16(acc[0][0], A0, c0.x, c0.y);
                MMA_F16(acc[0][1], A0, c0.z, c0.w);
                MMA_F16(acc[0][2], A0, c1.x, c1.y);
                MMA_F16(acc[0][3], A0, c1.z, c1.w);
                MMA_F16(acc[1][0], A1, c0.x, c0.y);
                MMA_F16(acc[1][1], A1, c0.z, c0.w);
                MMA_F16(acc[1][2], A1, c1.x, c1.y);
                MMA_F16(acc[1][3], A1, c1.z, c1.w);
            }

            if (nT < 64) {
#pragma unroll
                for (int m = 0; m < 2; m++) {
                    int eb0 = ebase + m * 16;
#pragma unroll
                    for (int q = 0; q < 4; q++) {
                        int col = n0 + q * 8 + ec2;
                        float2 v0 = make_float2(acc[m][q][0] + bzv[q][0], acc[m][q][1] + bzv[q][1]);
                        float2 v1 = make_float2(acc[m][q][2] + bzv[q][0], acc[m][q][3] + bzv[q][1]);
                        *(float2*)&g_G1[(size_t)eb0 * NG + col] = v0;
                        *(float2*)&g_G1[(size_t)(eb0 + 8) * NG + col] = v1;
                    }
                }
            } else if (nT < 68) {
                float* dvC = g_dv[t & 1];
#pragma unroll
                for (int m = 0; m < 2; m++) {
                    int eb0 = ebase + m * 16;
#pragma unroll
                    for (int q = 0; q < 4; q++) {
                        int dcol = n0 - NG + q * 8 + ec2;
                        dvC[eb0 * NSW + dcol]           = tanhf(acc[m][q][0] + bzv[q][0]);
                        dvC[eb0 * NSW + dcol + 1]       = tanhf(acc[m][q][1] + bzv[q][1]);
                        dvC[(eb0 + 8) * NSW + dcol]     = tanhf(acc[m][q][2] + bzv[q][0]);
                        dvC[(eb0 + 8) * NSW + dcol + 1] = tanhf(acc[m][q][3] + bzv[q][1]);
                    }
                }
            } else if (nT == 68) {
#pragma unroll
                for (int m = 0; m < 2; m++) {
                    int eb0 = ebase + m * 16;
                    if (ec2 < 3) {
                        g_ctrl[eb0 * 3 + ec2]       = acc[m][0][0] + bzv[0][0];
                        g_ctrl[(eb0 + 8) * 3 + ec2] = acc[m][0][2] + bzv[0][0];
                    }
                    if (ec2 + 1 < 3) {
                        g_ctrl[eb0 * 3 + ec2 + 1]       = acc[m][0][1] + bzv[0][1];
                        g_ctrl[(eb0 + 8) * 3 + ec2 + 1] = acc[m][0][3] + bzv[0][1];
                    }
                }
                BAR2();
                {
                    int b = mT * 128 + tid;   // tid < 128 here (warps 0-3)
                    float l0 = g_ctrl[b*3+0], l1 = g_ctrl[b*3+1], l2 = g_ctrl[b*3+2];
                    float mx = fmaxf(l0, fmaxf(l1, l2));
                    float e0 = expf(l0-mx), e1 = expf(l1-mx), e2 = expf(l2-mx);
                    float inv = 1.f / (e0+e1+e2);
                    float* cfC = g_cf[t & 1];
                    cfC[b] = e0*inv; cfC[256+b] = e1*inv; cfC[512+b] = e2*inv;
                }
            }
        } else if (t > 0) {
            // blend(t-1) on 12 warps, overlapped with MMA(t)
            const int ut = tid - 128;
            const float* cfP = g_cf[(t - 1) & 1];
            if (ut < 256) {
                cfo[ut]       = __ldcg(&cfP[ut]);
                cfo[256 + ut] = __ldcg(&cfP[256 + ut]);
                cfo[512 + ut] = __ldcg(&cfP[512 + ut]);
            }
            BAR3();
            run_blend(t - 1, bx, ut, cfo);
        }
        grid_bar(ep); ep++;

        // ======== phase B: gates path (lower 256) || x-convert(t+1) (upper 256) ========
        float* __restrict__ ht = outs + (size_t)t * NB * NH;

        if (tid < 256) {
            if (bx < 128) {
                const float* __restrict__ sold = g_stk[t & 1];
                const float* __restrict__ dvC = g_dv[t & 1];
                const float* __restrict__ cfC = g_cf[t & 1];
                const int mb0 = (bx >> 5) << 6;
                const int u0  = (bx & 31) << 4;
                cfs[tid]       = __ldcg(&cfC[tid]);
                cfs[256 + tid] = __ldcg(&cfC[256 + tid]);
                cfs[512 + tid] = __ldcg(&cfC[512 + tid]);
                BAR1();
                // stack_top -> fp16 A fragments (4 k per thread)
#pragma unroll
                for (int it = 0; it < 8; it++) {
                    int idx = tid + it * 256;
                    int bl = idx >> 5, k4 = (idx & 31) * 4;
                    int b = mb0 + bl;
                    float4 s0 = __ldcg((const float4*)&sold[(b * NSD + 0) * NSW + k4]);
                    float4 s1 = __ldcg((const float4*)&sold[(b * NSD + 1) * NSW + k4]);
                    float4 dd = __ldcg((const float4*)&dvC[b * NSW + k4]);
                    float no = cfs[512+b], pu = cfs[b], po = cfs[256+b];
                    store_sfrag2(Sfrag, bl, k4,
                                 no * s0.x + pu * dd.x + po * s1.x,
                                 no * s0.y + pu * dd.y + po * s1.y);
                    store_sfrag2(Sfrag, bl, k4 + 2,
                                 no * s0.z + pu * dd.z + po * s1.z,
                                 no * s0.w + pu * dd.w + po * s1.w);
                }
                // hoist LSTM inputs
                float2 hg[2][4], hc[2];
#pragma unroll
                for (int j = 0; j < 2; j++) {
                    int p = tid + j * 256;
                    int bl = p >> 3, uu2 = p & 7;
                    int b = mb0 + bl, u = u0 + uu2 * 2;
                    hg[j][0] = __ldcg((const float2*)&g_G1[(size_t)b * NG + u]);
                    hg[j][1] = __ldcg((const float2*)&g_G1[(size_t)b * NG + NH + u]);
                    hg[j][2] = __ldcg((const float2*)&g_G1[(size_t)b * NG + 2 * NH + u]);
                    hg[j][3] = __ldcg((const float2*)&g_G1[(size_t)b * NG + 3 * NH + u]);
                    hc[j] = *(const float2*)&g_c[b * NH + u];
                }
                BAR1();

                // gates GEMM on tensor pipe
                {
                    const int w8 = tid >> 5;
                    const int mt = w8 & 3, np = (w8 >> 2) * 2, ntb = (w8 >> 2) * 4;
                    float acc[4][4];
#pragma unroll
                    for (int q = 0; q < 4; q++)
#pragma unroll
                        for (int r = 0; r < 4; r++) acc[q][r] = 0.f;
#pragma unroll
                    for (int kc = 0; kc < 8; kc++) {
                        uint4 A = *(const uint4*)(smem + SMSF + ((kc * 4 + mt) << 9) + lane * 16);
                        uint4 wv0 = *(const uint4*)(smem + SMWS + (((kc * 4 + np) * 32 + lane) << 4));
                        uint4 wv1 = *(const uint4*)(smem + SMWS + (((kc * 4 + np + 1) * 32 + lane) << 4));
                        MMA_F16(acc[0], A, wv0.x, wv0.y);
                        MMA_F16(acc[1], A, wv0.z, wv0.w);
                        MMA_F16(acc[2], A, wv1.x, wv1.y);
                        MMA_F16(acc[3], A, wv1.z, wv1.w);
                    }
                    const int r0 = mt * 16 + er;
#pragma unroll
                    for (int q = 0; q < 4; q++) {
                        int col = (ntb + q) * 8 + ec2;
                        *(float2*)&gates_s[r0 * 64 + col]       = make_float2(acc[q][0], acc[q][1]);
                        *(float2*)&gates_s[(r0 + 8) * 64 + col] = make_float2(acc[q][2], acc[q][3]);
                    }
                }
                BAR1();

                // LSTM pointwise (paired units)
#pragma unroll
                for (int j = 0; j < 2; j++) {
                    int p = tid + j * 256;
                    int bl = p >> 3, uu2 = p & 7;
                    int b = mb0 + bl, u = u0 + uu2 * 2;
                    float2 gsi = *(const float2*)&gates_s[bl * 64 + uu2 * 2];
                    float2 gsf = *(const float2*)&gates_s[bl * 64 + 16 + uu2 * 2];
                    float2 gsg = *(const float2*)&gates_s[bl * 64 + 32 + uu2 * 2];
                    float2 gso = *(const float2*)&gates_s[bl * 64 + 48 + uu2 * 2];
                    float gi0 = gsi.x + hg[j][0].x, gi1 = gsi.y + hg[j][0].y;
                    float gf0 = gsf.x + hg[j][1].x, gf1 = gsf.y + hg[j][1].y;
                    float gg0 = gsg.x + hg[j][2].x, gg1 = gsg.y + hg[j][2].y;
                    float go0 = gso.x + hg[j][3].x, go1 = gso.y + hg[j][3].y;
                    float cn0 = sigf(gf0) * hc[j].x + sigf(gi0) * tanhf(gg0);
                    float cn1 = sigf(gf1) * hc[j].y + sigf(gi1) * tanhf(gg1);
                    float hh0 = sigf(go0) * tanhf(cn0);
                    float hh1 = sigf(go1) * tanhf(cn1);
                    *(float2*)&g_c[b * NH + u] = make_float2(cn0, cn1);
                    *(float2*)&ht[b * NH + u]  = make_float2(hh0, hh1);
                    store_zfrag2(b, u, hh0, hh1);
                }
            }
        } else {
            // x conversion for t+1, spread across all blocks' upper halves
            if (t + 1 < SEQT) {
                int idx = bx * 256 + (tid - 256);
                if (idx < NB * NIN / 2) {
                    const float* __restrict__ xn = x + (size_t)(t + 1) * NB * NIN;
                    int b = idx >> 7, k2 = idx & 127;
                    float2 xv = __ldcg((const float2*)&xn[b * NIN + k2 * 2]);
                    store_zfrag2(b, 512 + k2 * 2, xv.x, xv.y);
                }
            }
        }
        grid_bar(ep); ep++;
    }

    // final blend(SEQT-1): stk[1] -> stk[0]
    if (tid >= 128) {
        const int ut = tid - 128;
        const float* cfP = g_cf[(SEQT - 1) & 1];
        if (ut < 256) {
            cfo[ut]       = __ldcg(&cfP[ut]);
            cfo[256 + ut] = __ldcg(&cfP[256 + ut]);
            cfo[512 + ut] = __ldcg(&cfP[512 + ut]);
        }
        BAR3();
        run_blend(SEQT - 1, bx, ut, cfo);
    }
}

// ================= host =================
extern "C" void kernel_launch(void* const* d_in, const int* in_sizes, int n_in,
                              void* d_out, int out_size) {
    const float* x   = (const float*)d_in[0];
    const float* h0  = (const float*)d_in[1];
    const float* c0  = (const float*)d_in[2];
    const float* st0 = (const float*)d_in[3];
    const float* Aw  = (const float*)d_in[4];
    const float* Ab  = (const float*)d_in[5];
    const float* Dw  = (const float*)d_in[6];
    const float* Db  = (const float*)d_in[7];
    const float* Wih = (const float*)d_in[8];
    const float* Whh = (const float*)d_in[9];
    const float* bih = (const float*)d_in[10];
    const float* bhh = (const float*)d_in[11];

    float* outs  = (float*)d_out;
    float* h_out = outs + (size_t)SEQT * NB * NH;
    float* c_out = h_out + (size_t)NB * NH;
    float* s_out = c_out + (size_t)NB * NH;

    float* cbuf;  cudaGetSymbolAddress((void**)&cbuf, g_c);
    float* stbuf; cudaGetSymbolAddress((void**)&stbuf, g_stk);
    unsigned* flagbuf; cudaGetSymbolAddress((void**)&flagbuf, g_flags);

    cudaFuncSetAttribute(rnn_persist, cudaFuncAttributeMaxDynamicSharedMemorySize, SMTOTAL);

    cudaMemcpyAsync(cbuf,  c0,  (size_t)NB * NH * sizeof(float),        cudaMemcpyDeviceToDevice);
    cudaMemcpyAsync(stbuf, st0, (size_t)NB * NSD * NSW * sizeof(float), cudaMemcpyDeviceToDevice);
    cudaMemsetAsync(flagbuf, 0, NBLK * 32 * sizeof(unsigned));

    rnn_persist<<<NBLK, NTHR, SMTOTAL>>>(x, h0, outs, Wih, Whh, Dw, Aw, bih, bhh, Db, Ab);

    const size_t SSZ = (size_t)NB * NSD * NSW;
    cudaMemcpyAsync(h_out, outs + (size_t)(SEQT - 1) * NB * NH,
                    (size_t)NB * NH * sizeof(float), cudaMemcpyDeviceToDevice);
    cudaMemcpyAsync(c_out, cbuf, (size_t)NB * NH * sizeof(float), cudaMemcpyDeviceToDevice);
    cudaMemcpyAsync(s_out, stbuf, SSZ * sizeof(float), cudaMemcpyDeviceToDevice);
}

// round 15
// speedup vs baseline: 1.0051x; 1.0051x over previous
#include <cuda_runtime.h>
#include <cuda_fp16.h>
#include <math.h>
#include <stdint.h>

#define SEQT 1024
#define NB   256
#define NIN  256
#define NH   512
#define NSW  128
#define NSD  64
#define NG   2048            // 4*NH
#define KZ   768             // NH + NIN
#define NROWS 2240
#define NTOT 2179
#define NBLK 140             // 70 N-tiles x 2 M-halves
#define NKC  48              // 768/16
#define NTHR 512
#define GSTRIDE (NBLK * NTHR)

// phase A W fragment slice per nT (fp16): [kc(48)][nh(2)][lane(32)][8 halfs] = 24576 halfs
#define WSLICE_H 24576
// Z fragment: [kc(48)][mtile(16)][lane(32)][8 halfs]
#define ZTOT_H  196608
// phase B W_s fragment slice per u0: [kc(8)][ntp(4)][lane(32)][8 halfs]
#define WS_H 8192

// dynamic smem layout (bytes)
#define SMW     0                  // 49152: phase A W fragments
#define SMWS    49152              // 16384: phase B W_s fragments
#define SMSF    65536              // 16384: stack_top fp16 A fragments
#define SMGT    81920              // 16384: gates f32 [64][64]
#define SMCFO   98304              // 3072:  cf[3][256] previous step (blend)
#define SMTOTAL 101376

// ---- device scratch ----
__device__ __half g_Wfrag[70 * WSLICE_H];
__device__ __half g_WSfrag[32 * WS_H];
__device__ __half g_Zfrag[ZTOT_H];
__device__ float g_bz[NROWS];
__device__ float g_G1[NB * NG];
__device__ float g_dv[2][NB * NSW];   // double-buffered (blend lags one step)
__device__ float g_ctrl[NB * 3];
__device__ float g_cf[2][3 * NB];     // double-buffered softmax coefficients
__device__ float g_c[NB * NH];
__device__ float g_stk[2][NB * NSD * NSW];
__device__ unsigned g_flags[NBLK * 32];

// ---- helpers ----
__device__ __forceinline__ float sigf(float x) { return 1.f / (1.f + expf(-x)); }
__device__ __forceinline__ void store_zfrag(int b, int kk, float v) {
    int kc = kk >> 4, ko = kk & 15;
    int t   = ((b & 7) << 2) | ((ko & 7) >> 1);
    int reg = ((b >> 3) & 1) | (((ko >> 3) & 1) << 1);
    int idx = ((kc * 16 + (b >> 4)) * 32 + t) * 8 + reg * 2 + (ko & 1);
    g_Zfrag[idx] = __float2half(v);
}
__device__ __forceinline__ void store_zfrag2(int b, int kk, float v0, float v1) {
    int kc = kk >> 4, ko = kk & 15;
    int t   = ((b & 7) << 2) | ((ko & 7) >> 1);
    int reg = ((b >> 3) & 1) | (((ko >> 3) & 1) << 1);
    int idx = ((kc * 16 + (b >> 4)) * 32 + t) * 8 + reg * 2;
    *(__half2*)&g_Zfrag[idx] = __floats2half2_rn(v0, v1);
}
__device__ __forceinline__ void store_sfrag2(__half* base, int bl, int k, float v0, float v1) {
    int kc = k >> 4, ko = k & 15;
    int mt = bl >> 4, bm = bl & 15;
    int t   = ((bm & 7) << 2) | ((ko & 7) >> 1);
    int reg = ((bm >> 3) & 1) | (((ko >> 3) & 1) << 1);
    int idx = ((kc * 4 + mt) * 32 + t) * 8 + reg * 2;
    *(__half2*)&base[idx] = __floats2half2_rn(v0, v1);
}

#define MMA_F16(acc, A, b0, b1) asm volatile( \
    "mma.sync.aligned.m16n8k16.row.col.f32.f16.f16.f32 " \
    "{%0,%1,%2,%3},{%4,%5,%6,%7},{%8,%9},{%0,%1,%2,%3};" \
    : "+f"(acc[0]), "+f"(acc[1]), "+f"(acc[2]), "+f"(acc[3]) \
    : "r"(A.x), "r"(A.y), "r"(A.z), "r"(A.w), "r"(b0), "r"(b1))

#define BAR1() asm volatile("bar.sync 1, 256;" ::: "memory")   // lower 256 (gates)
#define BAR2() asm volatile("bar.sync 2, 256;" ::: "memory")   // lower 256 (ctrl)
#define BAR3() asm volatile("bar.sync 3, 256;" ::: "memory")   // upper 256 (blend cf)

// ---- distributed-flag grid barrier ----
__device__ __forceinline__ void grid_bar(int epoch) {
    const unsigned tgt = (unsigned)(epoch + 1);
    __syncthreads();
    if (threadIdx.x == 0) {
        asm volatile("st.release.gpu.u32 [%0], %1;"
                     :: "l"(&g_flags[blockIdx.x * 32]), "r"(tgt) : "memory");
    }
    if (threadIdx.x < NBLK) {
        unsigned v;
        do {
            asm volatile("ld.acquire.gpu.u32 %0, [%1];"
                         : "=r"(v) : "l"(&g_flags[threadIdx.x * 32]) : "memory");
        } while (v < tgt);
    }
    __syncthreads();
}

__device__ __forceinline__ float wval(int n, int k,
        const float* Whh, const float* Wih, const float* Dw, const float* Aw) {
    if (n < NG)        return (k < NH) ? Whh[n*NH + k] : Wih[n*(NIN+NSW) + (k-NH)];
    if (n < NG + NSW)  return (k < NH) ? Dw[(n-NG)*NH + k] : 0.f;
    if (n < NTOT)      return (k < NH) ? Aw[(n-NG-NSW)*NH + k] : 0.f;
    return 0.f;
}

// blend(tb): stk[tb&1] -> stk[(tb+1)&1] using cf(tb), dv(tb). Upper 256 threads.
__device__ __forceinline__ void run_blend(int tb, int bx, int ut, const float* cfo) {
    const float* __restrict__ sold = g_stk[tb & 1];
    float* __restrict__ snew = g_stk[(tb + 1) & 1];
    const float* __restrict__ dvO = g_dv[tb & 1];
    const int TOTR = NB * 8 * 32;
    int lo_ = (int)((long long)bx * TOTR / NBLK);
    int hi_ = (int)((long long)(bx + 1) * TOTR / NBLK);
    const float4 z4 = make_float4(0.f, 0.f, 0.f, 0.f);
    for (int run = lo_ + ut; run < hi_; run += 256) {
        int ww = run & 31;
        int q = run >> 5;
        int b = q >> 3, dr = q & 7;
        int d0 = dr << 3;
        float pu = cfo[b], po = cfo[256 + b], no = cfo[512 + b];
        const float* cb = &sold[b * NSD * NSW + ww * 4];
        float* ob = &snew[(b * NSD + d0) * NSW + ww * 4];
        float4 v[6];
        v[0] = d0 ? __ldcg((const float4*)(cb + (d0 - 1) * NSW))
                  : __ldcg((const float4*)&dvO[b * NSW + ww * 4]);
#pragma unroll
        for (int i = 0; i < 5; i++)
            v[i + 1] = __ldcg((const float4*)(cb + (d0 + i) * NSW));
#pragma unroll
        for (int i = 0; i < 4; i++) {
            float4 o;
            o.x = no * v[i+1].x + pu * v[i].x + po * v[i+2].x;
            o.y = no * v[i+1].y + pu * v[i].y + po * v[i+2].y;
            o.z = no * v[i+1].z + pu * v[i].z + po * v[i+2].z;
            o.w = no * v[i+1].w + pu * v[i].w + po * v[i+2].w;
            *(float4*)(ob + i * NSW) = o;
        }
        v[0] = v[4]; v[1] = v[5];
#pragma unroll
        for (int i = 0; i < 3; i++)
            v[i + 2] = __ldcg((const float4*)(cb + (d0 + 5 + i) * NSW));
        v[5] = (d0 + 8 < NSD) ? __ldcg((const float4*)(cb + (d0 + 8) * NSW)) : z4;
#pragma unroll
        for (int i = 0; i < 4; i++) {
            float4 o;
            o.x = no * v[i+1].x + pu * v[i].x + po * v[i+2].x;
            o.y = no * v[i+1].y + pu * v[i].y + po * v[i+2].y;
            o.z = no * v[i+1].z + pu * v[i].z + po * v[i+2].z;
            o.w = no * v[i+1].w + pu * v[i].w + po * v[i+2].w;
            *(float4*)(ob + (4 + i) * NSW) = o;
        }
    }
}

// ================= persistent kernel =================
__global__ void __launch_bounds__(NTHR, 1) rnn_persist(
    const float* __restrict__ x, const float* __restrict__ h0,
    float* __restrict__ outs, const float* __restrict__ Wih,
    const float* __restrict__ Whh, const float* __restrict__ Dw,
    const float* __restrict__ Aw,  const float* __restrict__ bih,
    const float* __restrict__ bhh, const float* __restrict__ Db,
    const float* __restrict__ Ab) {
    extern __shared__ char smem[];
    const int tid = threadIdx.x, bx = blockIdx.x;
    const int lane = tid & 31, w = tid >> 5;
    const int gtid = bx * NTHR + tid;

    // ---------- setup ----------
    {
        const long long WTOT = 70LL * WSLICE_H;
        for (long long i = gtid; i < WTOT; i += GSTRIDE) {
            int s = (int)(i / WSLICE_H);
            int j = (int)(i - (long long)s * WSLICE_H);
            int sub = j & 7, lane2 = (j >> 3) & 31, nh2 = (j >> 8) & 1, kc = j >> 9;
            int nt = nh2 * 2 + (sub >> 2);
            int jj = sub & 3;
            int nrow = s * 32 + nt * 8 + (lane2 >> 2);
            int kk = kc * 16 + (lane2 & 3) * 2 + ((jj >> 1) << 3) + (jj & 1);
            g_Wfrag[i] = __float2half(wval(nrow, kk, Whh, Wih, Dw, Aw));
        }
        for (int i = gtid; i < 32 * WS_H; i += GSTRIDE) {
            int s = i >> 13, j = i & (WS_H - 1);
            int sub = j & 7, lane2 = (j >> 3) & 31, ntp = (j >> 8) & 3, kc = j >> 10;
            int nt = ntp * 2 + (sub >> 2);
            int jj = sub & 3;
            int col = nt * 8 + (lane2 >> 2);
            int g = col >> 4, uu = col & 15;
            int jrow = g * NH + s * 16 + uu;
            int kk = kc * 16 + (lane2 & 3) * 2 + ((jj >> 1) << 3) + (jj & 1);
            g_WSfrag[i] = __float2half(Wih[jrow * (NIN + NSW) + NIN + kk]);
        }
        if (gtid < NROWS) {
            float b = 0.f;
            if (gtid < NG)          b = bih[gtid] + bhh[gtid];
            else if (gtid < NG+NSW) b = Db[gtid-NG];
            else if (gtid < NTOT)   b = Ab[gtid-NG-NSW];
            g_bz[gtid] = b;
        }
        for (int i = gtid; i < NB * NH; i += GSTRIDE)
            store_zfrag(i >> 9, i & 511, h0[i]);
        for (int i = gtid; i < NB * NIN; i += GSTRIDE)
            store_zfrag(i >> 8, 512 + (i & 255), x[i]);
    }
    grid_bar(0);

    const int nT = bx % 70, mT = bx / 70;
    const int n0 = nT * 32;
    const int mtile = mT * 8 + (w & 7);

    // load resident phase-A W slice (48 KB)
    {
        const uint4* src = (const uint4*)(g_Wfrag + (size_t)nT * WSLICE_H);
        uint4* dst = (uint4*)(smem + SMW);
#pragma unroll
        for (int i = 0; i < 6; i++) {
            uint4 v; const uint4* p = src + tid + i * NTHR;
            asm volatile("ld.global.cg.v4.u32 {%0,%1,%2,%3}, [%4];"
                         : "=r"(v.x), "=r"(v.y), "=r"(v.z), "=r"(v.w) : "l"(p));
            dst[tid + i * NTHR] = v;
        }
    }
    if (bx < 128) {
        const uint4* src = (const uint4*)(g_WSfrag + (size_t)(bx & 31) * WS_H);
        uint4* dst = (uint4*)(smem + SMWS);
#pragma unroll
        for (int i = 0; i < 2; i++) {
            uint4 v; const uint4* p = src + tid + i * NTHR;
            asm volatile("ld.global.cg.v4.u32 {%0,%1,%2,%3}, [%4];"
                         : "=r"(v.x), "=r"(v.y), "=r"(v.z), "=r"(v.w) : "l"(p));
            dst[tid + i * NTHR] = v;
        }
    }
    __syncthreads();

    const char* pB = smem + SMW + lane * 16;
    const char* pA = (const char*)g_Zfrag + mtile * 512 + lane * 16;
    __half* Sfrag  = (__half*)(smem + SMSF);
    float*  gates_s = (float*)(smem + SMGT);
    float*  cfo    = (float*)(smem + SMCFO);   // previous step (blend path)

    // phase A epilogue constants
    const int er = lane >> 2, ec2 = (lane & 3) << 1;
    const int eb0 = mT * 128 + (w & 7) * 16 + er;
    float bzv[4][2];
#pragma unroll
    for (int q = 0; q < 4; q++) {
        int col = n0 + q * 8 + ec2;
        bzv[q][0] = g_bz[col]; bzv[q][1] = g_bz[col + 1];
    }

    int ep = 1;
    for (int t = 0; t < SEQT; t++) {
        // ======== phase A window: warps 0-7 MMA(t) || warps 8-15 blend(t-1) ========
        if (w < 8) {
            float acc[4][4];
#pragma unroll
            for (int q = 0; q < 4; q++)
#pragma unroll
                for (int r = 0; r < 4; r++) acc[q][r] = 0.f;

            uint4 ab[8];
#pragma unroll
            for (int p = 0; p < 8; p++)
                ab[p] = __ldcg((const uint4*)(pA + p * 8192));
            uint4 bw0 = *(const uint4*)(pB);
            uint4 bw1 = *(const uint4*)(pB + 512);

            for (int kc = 0; kc < NKC; kc++) {
                uint4 A = ab[kc & 7];
                if (kc < NKC - 8)
                    ab[kc & 7] = __ldcg((const uint4*)(pA + (kc + 8) * 8192));
                uint4 c0 = bw0, c1 = bw1;
                if (kc < NKC - 1) {
                    bw0 = *(const uint4*)(pB + (((kc + 1) * 2 + 0) << 9));
                    bw1 = *(const uint4*)(pB + (((kc + 1) * 2 + 1) << 9));
                }
                MMA_F16(acc[0], A, c0.x, c0.y);
                MMA_F16(acc[1], A, c0.z, c0.w);
                MMA_F16(acc[2], A, c1.x, c1.y);
                MMA_F16(acc[3], A, c1.z, c1.w);
            }

            if (nT < 64) {
#pragma unroll
                for (int q = 0; q < 4; q++) {
                    int col = n0 + q * 8 + ec2;
                    float2 v0 = make_float2(acc[q][0] + bzv[q][0], acc[q][1] + bzv[q][1]);
                    float2 v1 = make_float2(acc[q][2] + bzv[q][0], acc[q][3] + bzv[q][1]);
                    *(float2*)&g_G1[(size_t)eb0 * NG + col] = v0;
                    *(float2*)&g_G1[(size_t)(eb0 + 8) * NG + col] = v1;
                }
            } else if (nT < 68) {
                float* dvC = g_dv[t & 1];
#pragma unroll
                for (int q = 0; q < 4; q++) {
                    int dcol = n0 - NG + q * 8 + ec2;
                    dvC[eb0 * NSW + dcol]           = tanhf(acc[q][0] + bzv[q][0]);
                    dvC[eb0 * NSW + dcol + 1]       = tanhf(acc[q][1] + bzv[q][1]);
                    dvC[(eb0 + 8) * NSW + dcol]     = tanhf(acc[q][2] + bzv[q][0]);
                    dvC[(eb0 + 8) * NSW + dcol + 1] = tanhf(acc[q][3] + bzv[q][1]);
                }
            } else if (nT == 68) {
                if (ec2 < 3) {
                    g_ctrl[eb0 * 3 + ec2]       = acc[0][0] + bzv[0][0];
                    g_ctrl[(eb0 + 8) * 3 + ec2] = acc[0][2] + bzv[0][0];
                }
                if (ec2 + 1 < 3) {
                    g_ctrl[eb0 * 3 + ec2 + 1]       = acc[0][1] + bzv[0][1];
                    g_ctrl[(eb0 + 8) * 3 + ec2 + 1] = acc[0][3] + bzv[0][1];
                }
                BAR2();
                if (tid < 128) {
                    int b = mT * 128 + tid;
                    float l0 = g_ctrl[b*3+0], l1 = g_ctrl[b*3+1], l2 = g_ctrl[b*3+2];
                    float mx = fmaxf(l0, fmaxf(l1, l2));
                    float e0 = expf(l0-mx), e1 = expf(l1-mx), e2 = expf(l2-mx);
                    float inv = 1.f / (e0+e1+e2);
                    float* cfC = g_cf[t & 1];
                    cfC[b] = e0*inv; cfC[256+b] = e1*inv; cfC[512+b] = e2*inv;
                }
            }
        } else if (t > 0) {
            // blend(t-1), overlapped with MMA(t)
            const int ut = tid - 256;
            const float* cfP = g_cf[(t - 1) & 1];
            cfo[ut]       = __ldcg(&cfP[ut]);
            cfo[256 + ut] = __ldcg(&cfP[256 + ut]);
            cfo[512 + ut] = __ldcg(&cfP[512 + ut]);
            BAR3();
            run_blend(t - 1, bx, ut, cfo);
        }
        grid_bar(ep); ep++;

        // ======== phase B: gates path (lower) || x-convert(t+1) (upper) ========
        float* __restrict__ ht = outs + (size_t)t * NB * NH;

        if (tid < 256) {
            if (bx < 128) {
                const float* __restrict__ sold = g_stk[t & 1];
                const float* __restrict__ dvC = g_dv[t & 1];
                const float* __restrict__ cfC = g_cf[t & 1];
                const int mb0 = (bx >> 5) << 6;
                const int u0  = (bx & 31) << 4;
                // direct cf loads (warp-uniform per bl -> broadcast), no smem staging / barrier
                float cpu[8], cpo[8], cno[8];
#pragma unroll
                for (int it = 0; it < 8; it++) {
                    int b = mb0 + (tid >> 5) + it * 8;
                    cpu[it] = __ldcg(&cfC[b]);
                    cpo[it] = __ldcg(&cfC[256 + b]);
                    cno[it] = __ldcg(&cfC[512 + b]);
                }
                // stack_top -> fp16 A fragments (4 k per thread)
#pragma unroll
                for (int it = 0; it < 8; it++) {
                    int idx = tid + it * 256;
                    int bl = idx >> 5, k4 = (idx & 31) * 4;
                    int b = mb0 + bl;
                    float4 s0 = __ldcg((const float4*)&sold[(b * NSD + 0) * NSW + k4]);
                    float4 s1 = __ldcg((const float4*)&sold[(b * NSD + 1) * NSW + k4]);
                    float4 dd = __ldcg((const float4*)&dvC[b * NSW + k4]);
                    float no = cno[it], pu = cpu[it], po = cpo[it];
                    store_sfrag2(Sfrag, bl, k4,
                                 no * s0.x + pu * dd.x + po * s1.x,
                                 no * s0.y + pu * dd.y + po * s1.y);
                    store_sfrag2(Sfrag, bl, k4 + 2,
                                 no * s0.z + pu * dd.z + po * s1.z,
                                 no * s0.w + pu * dd.w + po * s1.w);
                }
                // hoist LSTM inputs
                float2 hg[2][4], hc[2];
#pragma unroll
                for (int j = 0; j < 2; j++) {
                    int p = tid + j * 256;
                    int bl = p >> 3, uu2 = p & 7;
                    int b = mb0 + bl, u = u0 + uu2 * 2;
                    hg[j][0] = __ldcg((const float2*)&g_G1[(size_t)b * NG + u]);
                    hg[j][1] = __ldcg((const float2*)&g_G1[(size_t)b * NG + NH + u]);
                    hg[j][2] = __ldcg((const float2*)&g_G1[(size_t)b * NG + 2 * NH + u]);
                    hg[j][3] = __ldcg((const float2*)&g_G1[(size_t)b * NG + 3 * NH + u]);
                    hc[j] = *(const float2*)&g_c[b * NH + u];
                }
                BAR1();

                // gates GEMM on tensor pipe
                {
                    const int w8 = tid >> 5;
                    const int mt = w8 & 3, np = (w8 >> 2) * 2, ntb = (w8 >> 2) * 4;
                    float acc[4][4];
#pragma unroll
                    for (int q = 0; q < 4; q++)
#pragma unroll
                        for (int r = 0; r < 4; r++) acc[q][r] = 0.f;
#pragma unroll
                    for (int kc = 0; kc < 8; kc++) {
                        uint4 A = *(const uint4*)(smem + SMSF + ((kc * 4 + mt) << 9) + lane * 16);
                        uint4 wv0 = *(const uint4*)(smem + SMWS + (((kc * 4 + np) * 32 + lane) << 4));
                        uint4 wv1 = *(const uint4*)(smem + SMWS + (((kc * 4 + np + 1) * 32 + lane) << 4));
                        MMA_F16(acc[0], A, wv0.x, wv0.y);
                        MMA_F16(acc[1], A, wv0.z, wv0.w);
                        MMA_F16(acc[2], A, wv1.x, wv1.y);
                        MMA_F16(acc[3], A, wv1.z, wv1.w);
                    }
                    const int r0 = mt * 16 + er;
#pragma unroll
                    for (int q = 0; q < 4; q++) {
                        int col = (ntb + q) * 8 + ec2;
                        *(float2*)&gates_s[r0 * 64 + col]       = make_float2(acc[q][0], acc[q][1]);
                        *(float2*)&gates_s[(r0 + 8) * 64 + col] = make_float2(acc[q][2], acc[q][3]);
                    }
                }
                BAR1();

                // LSTM pointwise (paired units)
#pragma unroll
                for (int j = 0; j < 2; j++) {
                    int p = tid + j * 256;
                    int bl = p >> 3, uu2 = p & 7;
                    int b = mb0 + bl, u = u0 + uu2 * 2;
                    float2 gsi = *(const float2*)&gates_s[bl * 64 + uu2 * 2];
                    float2 gsf = *(const float2*)&gates_s[bl * 64 + 16 + uu2 * 2];
                    float2 gsg = *(const float2*)&gates_s[bl * 64 + 32 + uu2 * 2];
                    float2 gso = *(const float2*)&gates_s[bl * 64 + 48 + uu2 * 2];
                    float gi0 = gsi.x + hg[j][0].x, gi1 = gsi.y + hg[j][0].y;
                    float gf0 = gsf.x + hg[j][1].x, gf1 = gsf.y + hg[j][1].y;
                    float gg0 = gsg.x + hg[j][2].x, gg1 = gsg.y + hg[j][2].y;
                    float go0 = gso.x + hg[j][3].x, go1 = gso.y + hg[j][3].y;
                    float cn0 = sigf(gf0) * hc[j].x + sigf(gi0) * tanhf(gg0);
                    float cn1 = sigf(gf1) * hc[j].y + sigf(gi1) * tanhf(gg1);
                    float hh0 = sigf(go0) * tanhf(cn0);
                    float hh1 = sigf(go1) * tanhf(cn1);
                    *(float2*)&g_c[b * NH + u] = make_float2(cn0, cn1);
                    *(float2*)&ht[b * NH + u]  = make_float2(hh0, hh1);
                    store_zfrag2(b, u, hh0, hh1);
                }
            }
        } else {
            // x conversion for t+1, spread across all blocks' upper halves
            if (t + 1 < SEQT) {
                int idx = bx * 256 + (tid - 256);
                if (idx < NB * NIN / 2) {
                    const float* __restrict__ xn = x + (size_t)(t + 1) * NB * NIN;
                    int b = idx >> 7, k2 = idx & 127;
                    float2 xv = __ldcg((const float2*)&xn[b * NIN + k2 * 2]);
                    store_zfrag2(b, 512 + k2 * 2, xv.x, xv.y);
                }
            }
        }
        grid_bar(ep); ep++;
    }

    // final blend(SEQT-1): stk[1] -> stk[0]
    if (tid >= 256) {
        const int ut = tid - 256;
        const float* cfP = g_cf[(SEQT - 1) & 1];
        cfo[ut]       = __ldcg(&cfP[ut]);
        cfo[256 + ut] = __ldcg(&cfP[256 + ut]);
        cfo[512 + ut] = __ldcg(&cfP[512 + ut]);
        BAR3();
        run_blend(SEQT - 1, bx, ut, cfo);
    }
}

// ================= host =================
extern "C" void kernel_launch(void* const* d_in, const int* in_sizes, int n_in,
                              void* d_out, int out_size) {
    const float* x   = (const float*)d_in[0];
    const float* h0  = (const float*)d_in[1];
    const float* c0  = (const float*)d_in[2];
    const float* st0 = (const float*)d_in[3];
    const float* Aw  = (const float*)d_in[4];
    const float* Ab  = (const float*)d_in[5];
    const float* Dw  = (const float*)d_in[6];
    const float* Db  = (const float*)d_in[7];
    const float* Wih = (const float*)d_in[8];
    const float* Whh = (const float*)d_in[9];
    const float* bih = (const float*)d_in[10];
    const float* bhh = (const float*)d_in[11];

    float* outs  = (float*)d_out;
    float* h_out = outs + (size_t)SEQT * NB * NH;
    float* c_out = h_out + (size_t)NB * NH;
    float* s_out = c_out + (size_t)NB * NH;

    float* cbuf;  cudaGetSymbolAddress((void**)&cbuf, g_c);
    float* stbuf; cudaGetSymbolAddress((void**)&stbuf, g_stk);
    unsigned* flagbuf; cudaGetSymbolAddress((void**)&flagbuf, g_flags);

    cudaFuncSetAttribute(rnn_persist, cudaFuncAttributeMaxDynamicSharedMemorySize, SMTOTAL);

    cudaMemcpyAsync(cbuf,  c0,  (size_t)NB * NH * sizeof(float),        cudaMemcpyDeviceToDevice);
    cudaMemcpyAsync(stbuf, st0, (size_t)NB * NSD * NSW * sizeof(float), cudaMemcpyDeviceToDevice);
    cudaMemsetAsync(flagbuf, 0, NBLK * 32 * sizeof(unsigned));

    rnn_persist<<<NBLK, NTHR, SMTOTAL>>>(x, h0, outs, Wih, Whh, Dw, Aw, bih, bhh, Db, Ab);

    const size_t SSZ = (size_t)NB * NSD * NSW;
    cudaMemcpyAsync(h_out, outs + (size_t)(SEQT - 1) * NB * NH,
                    (size_t)NB * NH * sizeof(float), cudaMemcpyDeviceToDevice);
    cudaMemcpyAsync(c_out, cbuf, (size_t)NB * NH * sizeof(float), cudaMemcpyDeviceToDevice);
    cudaMemcpyAsync(s_out, stbuf, SSZ * sizeof(float), cudaMemcpyDeviceToDevice);
}

// round 16
// speedup vs baseline: 1.0396x; 1.0343x over previous
#include <cuda_runtime.h>
#include <cuda_fp16.h>
#include <math.h>
#include <stdint.h>

#define SEQT 1024
#define NB   256
#define NIN  256
#define NH   512
#define NSW  128
#define NSD  64
#define NG   2048            // 4*NH
#define KZ   768             // NH + NIN
#define NROWS 2240
#define NTOT 2179
#define NBLK 140             // 70 N-tiles x 2 M-halves
#define NKC  48              // 768/16
#define NTHR 512
#define GSTRIDE (NBLK * NTHR)

// phase A W fragment slice per nT (fp16): [kc(48)][nh(2)][lane(32)][8 halfs] = 24576 halfs
#define WSLICE_H 24576
// Z fragment: [kc(48)][mtile(16)][lane(32)][8 halfs]
#define ZTOT_H  196608
// phase B W_s fragment slice per u0: [kc(8)][ntp(4)][lane(32)][8 halfs]
#define WS_H 8192

// dynamic smem layout (bytes)
#define SMW     0                  // 49152: phase A W fragments
#define SMWS    49152              // 16384: phase B W_s fragments
#define SMSF    65536              // 16384: stack_top fp16 A fragments
#define SMGT    81920              // 16384: gates f32 [64][64]
#define SMCF    98304              // 3072:  cf[3][256] current step (gates)
#define SMCFO   101376             // 3072:  cf[3][256] blend step
#define SMTOTAL 104448

// ---- device scratch ----
__device__ __half g_Wfrag[70 * WSLICE_H];
__device__ __half g_WSfrag[32 * WS_H];
__device__ __half g_Zfrag[ZTOT_H];
__device__ float g_bz[NROWS];
__device__ float g_G1[NB * NG];
__device__ float g_dv[2][NB * NSW];   // double-buffered (blend lags one step)
__device__ float g_ctrl[NB * 3];
__device__ float g_cf[2][3 * NB];     // double-buffered softmax coefficients
__device__ float g_c[NB * NH];
__device__ float g_stk[2][NB * NSD * NSW];
__device__ unsigned g_flags[NBLK * 32];

// ---- helpers ----
__device__ __forceinline__ float sigf(float x) { return 1.f / (1.f + expf(-x)); }
__device__ __forceinline__ void store_zfrag(int b, int kk, float v) {
    int kc = kk >> 4, ko = kk & 15;
    int t   = ((b & 7) << 2) | ((ko & 7) >> 1);
    int reg = ((b >> 3) & 1) | (((ko >> 3) & 1) << 1);
    int idx = ((kc * 16 + (b >> 4)) * 32 + t) * 8 + reg * 2 + (ko & 1);
    g_Zfrag[idx] = __float2half(v);
}
__device__ __forceinline__ void store_zfrag2(int b, int kk, float v0, float v1) {
    int kc = kk >> 4, ko = kk & 15;
    int t   = ((b & 7) << 2) | ((ko & 7) >> 1);
    int reg = ((b >> 3) & 1) | (((ko >> 3) & 1) << 1);
    int idx = ((kc * 16 + (b >> 4)) * 32 + t) * 8 + reg * 2;
    *(__half2*)&g_Zfrag[idx] = __floats2half2_rn(v0, v1);
}
__device__ __forceinline__ void store_sfrag2(__half* base, int bl, int k, float v0, float v1) {
    int kc = k >> 4, ko = k & 15;
    int mt = bl >> 4, bm = bl & 15;
    int t   = ((bm & 7) << 2) | ((ko & 7) >> 1);
    int reg = ((bm >> 3) & 1) | (((ko >> 3) & 1) << 1);
    int idx = ((kc * 4 + mt) * 32 + t) * 8 + reg * 2;
    *(__half2*)&base[idx] = __floats2half2_rn(v0, v1);
}

#define MMA_F16(acc, A, b0, b1) asm volatile( \
    "mma.sync.aligned.m16n8k16.row.col.f32.f16.f16.f32 " \
    "{%0,%1,%2,%3},{%4,%5,%6,%7},{%8,%9},{%0,%1,%2,%3};" \
    : "+f"(acc[0]), "+f"(acc[1]), "+f"(acc[2]), "+f"(acc[3]) \
    : "r"(A.x), "r"(A.y), "r"(A.z), "r"(A.w), "r"(b0), "r"(b1))

#define BAR1() asm volatile("bar.sync 1, 256;" ::: "memory")   // lower 256 (gates)
#define BAR2() asm volatile("bar.sync 2, 256;" ::: "memory")   // lower 256 (ctrl)
#define BAR3() asm volatile("bar.sync 3, 256;" ::: "memory")   // upper 256 (blend cf)

// ---- distributed-flag grid barrier ----
__device__ __forceinline__ void grid_bar(int epoch) {
    const unsigned tgt = (unsigned)(epoch + 1);
    __syncthreads();
    if (threadIdx.x == 0) {
        asm volatile("st.release.gpu.u32 [%0], %1;"
                     :: "l"(&g_flags[blockIdx.x * 32]), "r"(tgt) : "memory");
    }
    if (threadIdx.x < NBLK) {
        unsigned v;
        do {
            asm volatile("ld.acquire.gpu.u32 %0, [%1];"
                         : "=r"(v) : "l"(&g_flags[threadIdx.x * 32]) : "memory");
        } while (v < tgt);
    }
    __syncthreads();
}

__device__ __forceinline__ float wval(int n, int k,
        const float* Whh, const float* Wih, const float* Dw, const float* Aw) {
    if (n < NG)        return (k < NH) ? Whh[n*NH + k] : Wih[n*(NIN+NSW) + (k-NH)];
    if (n < NG + NSW)  return (k < NH) ? Dw[(n-NG)*NH + k] : 0.f;
    if (n < NTOT)      return (k < NH) ? Aw[(n-NG-NSW)*NH + k] : 0.f;
    return 0.f;
}

// blend(tb) over run range [lo_, hi_): stk[tb&1] -> stk[(tb+1)&1], cf from cfo, dv(tb).
// Executed by upper 256 threads (ut 0..255).
__device__ __forceinline__ void run_blend(int tb, int ut, int lo_, int hi_, const float* cfo) {
    const float* __restrict__ sold = g_stk[tb & 1];
    float* __restrict__ snew = g_stk[(tb + 1) & 1];
    const float* __restrict__ dvO = g_dv[tb & 1];
    const float4 z4 = make_float4(0.f, 0.f, 0.f, 0.f);
    for (int run = lo_ + ut; run < hi_; run += 256) {
        int ww = run & 31;
        int q = run >> 5;
        int b = q >> 3, dr = q & 7;
        int d0 = dr << 3;
        float pu = cfo[b], po = cfo[256 + b], no = cfo[512 + b];
        const float* cb = &sold[b * NSD * NSW + ww * 4];
        float* ob = &snew[(b * NSD + d0) * NSW + ww * 4];
        float4 v[6];
        v[0] = d0 ? __ldcg((const float4*)(cb + (d0 - 1) * NSW))
                  : __ldcg((const float4*)&dvO[b * NSW + ww * 4]);
#pragma unroll
        for (int i = 0; i < 5; i++)
            v[i + 1] = __ldcg((const float4*)(cb + (d0 + i) * NSW));
#pragma unroll
        for (int i = 0; i < 4; i++) {
            float4 o;
            o.x = no * v[i+1].x + pu * v[i].x + po * v[i+2].x;
            o.y = no * v[i+1].y + pu * v[i].y + po * v[i+2].y;
            o.z = no * v[i+1].z + pu * v[i].z + po * v[i+2].z;
            o.w = no * v[i+1].w + pu * v[i].w + po * v[i+2].w;
            *(float4*)(ob + i * NSW) = o;
        }
        v[0] = v[4]; v[1] = v[5];
#pragma unroll
        for (int i = 0; i < 3; i++)
            v[i + 2] = __ldcg((const float4*)(cb + (d0 + 5 + i) * NSW));
        v[5] = (d0 + 8 < NSD) ? __ldcg((const float4*)(cb + (d0 + 8) * NSW)) : z4;
#pragma unroll
        for (int i = 0; i < 4; i++) {
            float4 o;
            o.x = no * v[i+1].x + pu * v[i].x + po * v[i+2].x;
            o.y = no * v[i+1].y + pu * v[i].y + po * v[i+2].y;
            o.z = no * v[i+1].z + pu * v[i].z + po * v[i+2].z;
            o.w = no * v[i+1].w + pu * v[i].w + po * v[i+2].w;
            *(float4*)(ob + (4 + i) * NSW) = o;
        }
    }
}

// ================= persistent kernel =================
__global__ void __launch_bounds__(NTHR, 1) rnn_persist(
    const float* __restrict__ x, const float* __restrict__ h0,
    float* __restrict__ outs, const float* __restrict__ Wih,
    const float* __restrict__ Whh, const float* __restrict__ Dw,
    const float* __restrict__ Aw,  const float* __restrict__ bih,
    const float* __restrict__ bhh, const float* __restrict__ Db,
    const float* __restrict__ Ab) {
    extern __shared__ char smem[];
    const int tid = threadIdx.x, bx = blockIdx.x;
    const int lane = tid & 31, w = tid >> 5;
    const int gtid = bx * NTHR + tid;

    // ---------- setup ----------
    {
        const long long WTOT = 70LL * WSLICE_H;
        for (long long i = gtid; i < WTOT; i += GSTRIDE) {
            int s = (int)(i / WSLICE_H);
            int j = (int)(i - (long long)s * WSLICE_H);
            int sub = j & 7, lane2 = (j >> 3) & 31, nh2 = (j >> 8) & 1, kc = j >> 9;
            int nt = nh2 * 2 + (sub >> 2);
            int jj = sub & 3;
            int nrow = s * 32 + nt * 8 + (lane2 >> 2);
            int kk = kc * 16 + (lane2 & 3) * 2 + ((jj >> 1) << 3) + (jj & 1);
            g_Wfrag[i] = __float2half(wval(nrow, kk, Whh, Wih, Dw, Aw));
        }
        for (int i = gtid; i < 32 * WS_H; i += GSTRIDE) {
            int s = i >> 13, j = i & (WS_H - 1);
            int sub = j & 7, lane2 = (j >> 3) & 31, ntp = (j >> 8) & 3, kc = j >> 10;
            int nt = ntp * 2 + (sub >> 2);
            int jj = sub & 3;
            int col = nt * 8 + (lane2 >> 2);
            int g = col >> 4, uu = col & 15;
            int jrow = g * NH + s * 16 + uu;
            int kk = kc * 16 + (lane2 & 3) * 2 + ((jj >> 1) << 3) + (jj & 1);
            g_WSfrag[i] = __float2half(Wih[jrow * (NIN + NSW) + NIN + kk]);
        }
        if (gtid < NROWS) {
            float b = 0.f;
            if (gtid < NG)          b = bih[gtid] + bhh[gtid];
            else if (gtid < NG+NSW) b = Db[gtid-NG];
            else if (gtid < NTOT)   b = Ab[gtid-NG-NSW];
            g_bz[gtid] = b;
        }
        for (int i = gtid; i < NB * NH; i += GSTRIDE)
            store_zfrag(i >> 9, i & 511, h0[i]);
        for (int i = gtid; i < NB * NIN; i += GSTRIDE)
            store_zfrag(i >> 8, 512 + (i & 255), x[i]);
    }
    grid_bar(0);

    const int nT = bx % 70, mT = bx / 70;
    const int n0 = nT * 32;
    const int mtile = mT * 8 + (w & 7);

    // blend run-range for this block, split into B-window half and A-window half
    const int TOTR = NB * 8 * 32;
    const int blo = (int)((long long)bx * TOTR / NBLK);
    const int bhi = (int)((long long)(bx + 1) * TOTR / NBLK);
    const int bmid = (blo + bhi) >> 1;

    // load resident phase-A W slice (48 KB)
    {
        const uint4* src = (const uint4*)(g_Wfrag + (size_t)nT * WSLICE_H);
        uint4* dst = (uint4*)(smem + SMW);
#pragma unroll
        for (int i = 0; i < 6; i++) {
            uint4 v; const uint4* p = src + tid + i * NTHR;
            asm volatile("ld.global.cg.v4.u32 {%0,%1,%2,%3}, [%4];"
                         : "=r"(v.x), "=r"(v.y), "=r"(v.z), "=r"(v.w) : "l"(p));
            dst[tid + i * NTHR] = v;
        }
    }
    if (bx < 128) {
        const uint4* src = (const uint4*)(g_WSfrag + (size_t)(bx & 31) * WS_H);
        uint4* dst = (uint4*)(smem + SMWS);
#pragma unroll
        for (int i = 0; i < 2; i++) {
            uint4 v; const uint4* p = src + tid + i * NTHR;
            asm volatile("ld.global.cg.v4.u32 {%0,%1,%2,%3}, [%4];"
                         : "=r"(v.x), "=r"(v.y), "=r"(v.z), "=r"(v.w) : "l"(p));
            dst[tid + i * NTHR] = v;
        }
    }
    __syncthreads();

    const char* pB = smem + SMW + lane * 16;
    const char* pA = (const char*)g_Zfrag + mtile * 512 + lane * 16;
    __half* Sfrag  = (__half*)(smem + SMSF);
    float*  gates_s = (float*)(smem + SMGT);
    float*  cfs    = (float*)(smem + SMCF);    // current step (gates path)
    float*  cfo    = (float*)(smem + SMCFO);   // blend step

    // phase A epilogue constants
    const int er = lane >> 2, ec2 = (lane & 3) << 1;
    const int eb0 = mT * 128 + (w & 7) * 16 + er;
    float bzv[4][2];
#pragma unroll
    for (int q = 0; q < 4; q++) {
        int col = n0 + q * 8 + ec2;
        bzv[q][0] = g_bz[col]; bzv[q][1] = g_bz[col + 1];
    }

    int ep = 1;
    for (int t = 0; t < SEQT; t++) {
        // ======== phase A window: warps 0-7 MMA(t) || warps 8-15 blend(t-1) part2 ========
        if (w < 8) {
            float acc[4][4];
#pragma unroll
            for (int q = 0; q < 4; q++)
#pragma unroll
                for (int r = 0; r < 4; r++) acc[q][r] = 0.f;

            uint4 ab[8];
#pragma unroll
            for (int p = 0; p < 8; p++)
                ab[p] = __ldcg((const uint4*)(pA + p * 8192));

            for (int kc = 0; kc < NKC; kc++) {
                uint4 A = ab[kc & 7];
                if (kc < NKC - 8)
                    ab[kc & 7] = __ldcg((const uint4*)(pA + (kc + 8) * 8192));
                uint4 wv0 = *(const uint4*)(pB + ((kc * 2 + 0) << 9));
                uint4 wv1 = *(const uint4*)(pB + ((kc * 2 + 1) << 9));
                MMA_F16(acc[0], A, wv0.x, wv0.y);
                MMA_F16(acc[1], A, wv0.z, wv0.w);
                MMA_F16(acc[2], A, wv1.x, wv1.y);
                MMA_F16(acc[3], A, wv1.z, wv1.w);
            }

            if (nT < 64) {
#pragma unroll
                for (int q = 0; q < 4; q++) {
                    int col = n0 + q * 8 + ec2;
                    float2 v0 = make_float2(acc[q][0] + bzv[q][0], acc[q][1] + bzv[q][1]);
                    float2 v1 = make_float2(acc[q][2] + bzv[q][0], acc[q][3] + bzv[q][1]);
                    *(float2*)&g_G1[(size_t)eb0 * NG + col] = v0;
                    *(float2*)&g_G1[(size_t)(eb0 + 8) * NG + col] = v1;
                }
            } else if (nT < 68) {
                float* dvC = g_dv[t & 1];
#pragma unroll
                for (int q = 0; q < 4; q++) {
                    int dcol = n0 - NG + q * 8 + ec2;
                    dvC[eb0 * NSW + dcol]           = tanhf(acc[q][0] + bzv[q][0]);
                    dvC[eb0 * NSW + dcol + 1]       = tanhf(acc[q][1] + bzv[q][1]);
                    dvC[(eb0 + 8) * NSW + dcol]     = tanhf(acc[q][2] + bzv[q][0]);
                    dvC[(eb0 + 8) * NSW + dcol + 1] = tanhf(acc[q][3] + bzv[q][1]);
                }
            } else if (nT == 68) {
                if (ec2 < 3) {
                    g_ctrl[eb0 * 3 + ec2]       = acc[0][0] + bzv[0][0];
                    g_ctrl[(eb0 + 8) * 3 + ec2] = acc[0][2] + bzv[0][0];
                }
                if (ec2 + 1 < 3) {
                    g_ctrl[eb0 * 3 + ec2 + 1]       = acc[0][1] + bzv[0][1];
                    g_ctrl[(eb0 + 8) * 3 + ec2 + 1] = acc[0][3] + bzv[0][1];
                }
                BAR2();
                if (tid < 128) {
                    int b = mT * 128 + tid;
                    float l0 = g_ctrl[b*3+0], l1 = g_ctrl[b*3+1], l2 = g_ctrl[b*3+2];
                    float mx = fmaxf(l0, fmaxf(l1, l2));
                    float e0 = expf(l0-mx), e1 = expf(l1-mx), e2 = expf(l2-mx);
                    float inv = 1.f / (e0+e1+e2);
                    float* cfC = g_cf[t & 1];
                    cfC[b] = e0*inv; cfC[256+b] = e1*inv; cfC[512+b] = e2*inv;
                }
            }
        } else if (t > 0) {
            // blend(t-1) part2 [bmid, bhi), overlapped with MMA(t).
            // cfo already holds cf(t-1): staged during phase B(t-1); ordered by grid_bar.
            run_blend(t - 1, tid - 256, bmid, bhi, cfo);
        }
        grid_bar(ep); ep++;

        // ======== phase B: gates path (lower) || x-convert + blend(t) part1 (upper) ========
        float* __restrict__ ht = outs + (size_t)t * NB * NH;

        if (tid < 256) {
            if (bx < 128) {
                const float* __restrict__ sold = g_stk[t & 1];
                const float* __restrict__ dvC = g_dv[t & 1];
                const float* __restrict__ cfC = g_cf[t & 1];
                const int mb0 = (bx >> 5) << 6;
                const int u0  = (bx & 31) << 4;
                cfs[tid]       = __ldcg(&cfC[tid]);
                cfs[256 + tid] = __ldcg(&cfC[256 + tid]);
                cfs[512 + tid] = __ldcg(&cfC[512 + tid]);
                BAR1();
                // stack_top -> fp16 A fragments (4 k per thread)
#pragma unroll
                for (int it = 0; it < 8; it++) {
                    int idx = tid + it * 256;
                    int bl = idx >> 5, k4 = (idx & 31) * 4;
                    int b = mb0 + bl;
                    float4 s0 = __ldcg((const float4*)&sold[(b * NSD + 0) * NSW + k4]);
                    float4 s1 = __ldcg((const float4*)&sold[(b * NSD + 1) * NSW + k4]);
                    float4 dd = __ldcg((const float4*)&dvC[b * NSW + k4]);
                    float no = cfs[512+b], pu = cfs[b], po = cfs[256+b];
                    store_sfrag2(Sfrag, bl, k4,
                                 no * s0.x + pu * dd.x + po * s1.x,
                                 no * s0.y + pu * dd.y + po * s1.y);
                    store_sfrag2(Sfrag, bl, k4 + 2,
                                 no * s0.z + pu * dd.z + po * s1.z,
                                 no * s0.w + pu * dd.w + po * s1.w);
                }
                // hoist LSTM inputs
                float2 hg[2][4], hc[2];
#pragma unroll
                for (int j = 0; j < 2; j++) {
                    int p = tid + j * 256;
                    int bl = p >> 3, uu2 = p & 7;
                    int b = mb0 + bl, u = u0 + uu2 * 2;
                    hg[j][0] = __ldcg((const float2*)&g_G1[(size_t)b * NG + u]);
                    hg[j][1] = __ldcg((const float2*)&g_G1[(size_t)b * NG + NH + u]);
                    hg[j][2] = __ldcg((const float2*)&g_G1[(size_t)b * NG + 2 * NH + u]);
                    hg[j][3] = __ldcg((const float2*)&g_G1[(size_t)b * NG + 3 * NH + u]);
                    hc[j] = *(const float2*)&g_c[b * NH + u];
                }
                BAR1();

                // gates GEMM on tensor pipe
                {
                    const int w8 = tid >> 5;
                    const int mt = w8 & 3, np = (w8 >> 2) * 2, ntb = (w8 >> 2) * 4;
                    float acc[4][4];
#pragma unroll
                    for (int q = 0; q < 4; q++)
#pragma unroll
                        for (int r = 0; r < 4; r++) acc[q][r] = 0.f;
#pragma unroll
                    for (int kc = 0; kc < 8; kc++) {
                        uint4 A = *(const uint4*)(smem + SMSF + ((kc * 4 + mt) << 9) + lane * 16);
                        uint4 wv0 = *(const uint4*)(smem + SMWS + (((kc * 4 + np) * 32 + lane) << 4));
                        uint4 wv1 = *(const uint4*)(smem + SMWS + (((kc * 4 + np + 1) * 32 + lane) << 4));
                        MMA_F16(acc[0], A, wv0.x, wv0.y);
                        MMA_F16(acc[1], A, wv0.z, wv0.w);
                        MMA_F16(acc[2], A, wv1.x, wv1.y);
                        MMA_F16(acc[3], A, wv1.z, wv1.w);
                    }
                    const int r0 = mt * 16 + er;
#pragma unroll
                    for (int q = 0; q < 4; q++) {
                        int col = (ntb + q) * 8 + ec2;
                        *(float2*)&gates_s[r0 * 64 + col]       = make_float2(acc[q][0], acc[q][1]);
                        *(float2*)&gates_s[(r0 + 8) * 64 + col] = make_float2(acc[q][2], acc[q][3]);
                    }
                }
                BAR1();

                // LSTM pointwise (paired units)
#pragma unroll
                for (int j = 0; j < 2; j++) {
                    int p = tid + j * 256;
                    int bl = p >> 3, uu2 = p & 7;
                    int b = mb0 + bl, u = u0 + uu2 * 2;
                    float2 gsi = *(const float2*)&gates_s[bl * 64 + uu2 * 2];
                    float2 gsf = *(const float2*)&gates_s[bl * 64 + 16 + uu2 * 2];
                    float2 gsg = *(const float2*)&gates_s[bl * 64 + 32 + uu2 * 2];
                    float2 gso = *(const float2*)&gates_s[bl * 64 + 48 + uu2 * 2];
                    float gi0 = gsi.x + hg[j][0].x, gi1 = gsi.y + hg[j][0].y;
                    float gf0 = gsf.x + hg[j][1].x, gf1 = gsf.y + hg[j][1].y;
                    float gg0 = gsg.x + hg[j][2].x, gg1 = gsg.y + hg[j][2].y;
                    float go0 = gso.x + hg[j][3].x, go1 = gso.y + hg[j][3].y;
                    float cn0 = sigf(gf0) * hc[j].x + sigf(gi0) * tanhf(gg0);
                    float cn1 = sigf(gf1) * hc[j].y + sigf(gi1) * tanhf(gg1);
                    float hh0 = sigf(go0) * tanhf(cn0);
                    float hh1 = sigf(go1) * tanhf(cn1);
                    *(float2*)&g_c[b * NH + u] = make_float2(cn0, cn1);
                    *(float2*)&ht[b * NH + u]  = make_float2(hh0, hh1);
                    store_zfrag2(b, u, hh0, hh1);
                }
            }
        } else {
            const int ut = tid - 256;
            // x conversion for t+1 (blocks 0-127)
            if (t + 1 < SEQT) {
                int idx = bx * 256 + ut;
                if (idx < NB * NIN / 2) {
                    const float* __restrict__ xn = x + (size_t)(t + 1) * NB * NIN;
                    int b = idx >> 7, k2 = idx & 127;
                    float2 xv = __ldcg((const float2*)&xn[b * NIN + k2 * 2]);
                    store_zfrag2(b, 512 + k2 * 2, xv.x, xv.y);
                }
            }
            // stage cf(t) into cfo and run blend(t) part1 [blo, bmid)
            const float* cfC = g_cf[t & 1];
            cfo[ut]       = __ldcg(&cfC[ut]);
            cfo[256 + ut] = __ldcg(&cfC[256 + ut]);
            cfo[512 + ut] = __ldcg(&cfC[512 + ut]);
            BAR3();
            run_blend(t, ut, blo, bmid, cfo);
        }
        grid_bar(ep); ep++;
    }

    // final: blend(SEQT-1) part2 (cfo holds cf(SEQT-1) from last phase B)
    if (tid >= 256) {
        run_blend(SEQT - 1, tid - 256, bmid, bhi, cfo);
    }
}

// ================= host =================
extern "C" void kernel_launch(void* const* d_in, const int* in_sizes, int n_in,
                              void* d_out, int out_size) {
    const float* x   = (const float*)d_in[0];
    const float* h0  = (const float*)d_in[1];
    const float* c0  = (const float*)d_in[2];
    const float* st0 = (const float*)d_in[3];
    const float* Aw  = (const float*)d_in[4];
    const float* Ab  = (const float*)d_in[5];
    const float* Dw  = (const float*)d_in[6];
    const float* Db  = (const float*)d_in[7];
    const float* Wih = (const float*)d_in[8];
    const float* Whh = (const float*)d_in[9];
    const float* bih = (const float*)d_in[10];
    const float* bhh = (const float*)d_in[11];

    float* outs  = (float*)d_out;
    float* h_out = outs + (size_t)SEQT * NB * NH;
    float* c_out = h_out + (size_t)NB * NH;
    float* s_out = c_out + (size_t)NB * NH;

    float* cbuf;  cudaGetSymbolAddress((void**)&cbuf, g_c);
    float* stbuf; cudaGetSymbolAddress((void**)&stbuf, g_stk);
    unsigned* flagbuf; cudaGetSymbolAddress((void**)&flagbuf, g_flags);

    cudaFuncSetAttribute(rnn_persist, cudaFuncAttributeMaxDynamicSharedMemorySize, SMTOTAL);

    cudaMemcpyAsync(cbuf,  c0,  (size_t)NB * NH * sizeof(float),        cudaMemcpyDeviceToDevice);
    cudaMemcpyAsync(stbuf, st0, (size_t)NB * NSD * NSW * sizeof(float), cudaMemcpyDeviceToDevice);
    cudaMemsetAsync(flagbuf, 0, NBLK * 32 * sizeof(unsigned));

    rnn_persist<<<NBLK, NTHR, SMTOTAL>>>(x, h0, outs, Wih, Whh, Dw, Aw, bih, bhh, Db, Ab);

    const size_t SSZ = (size_t)NB * NSD * NSW;
    cudaMemcpyAsync(h_out, outs + (size_t)(SEQT - 1) * NB * NH,
                    (size_t)NB * NH * sizeof(float), cudaMemcpyDeviceToDevice);
    cudaMemcpyAsync(c_out, cbuf, (size_t)NB * NH * sizeof(float), cudaMemcpyDeviceToDevice);
    cudaMemcpyAsync(s_out, stbuf, SSZ * sizeof(float), cudaMemcpyDeviceToDevice);
}